// round 1
// baseline (speedup 1.0000x reference)
#include <cuda_runtime.h>
#include <math.h>

// Problem constants
#define CDIM   192
#define OC3    576
#define HWDIM  256
#define WS     8
#define SHIFT  4
#define HEADS  6
#define CPH    32
#define PIX    64     // pixels per 8x8 window
#define NWIN   4096   // 4 * 32 * 32

// Shared memory layout (floats)
#define XS_OFF   0                    // 192*64 = 12288 floats (x window; reused as attention output)
#define QS_OFF   12288                // 576*65 = 37440 floats (qkv after dwconv, stride 65)
#define ST_OFF   (12288 + 37440)      // 6144 floats (GEMM staging 64*64; reused as attn matrices 6*1024)
#define SMEM_FLOATS (12288 + 37440 + 6144)   // 55872 floats = 223488 bytes

__global__ __launch_bounds__(256, 1)
void win_attn_kernel(const float* __restrict__ x,
                     const float* __restrict__ qkv_w,
                     const float* __restrict__ dw_w,
                     const float* __restrict__ proj_w,
                     const float* __restrict__ temperature,
                     float* __restrict__ out)
{
    extern __shared__ float sm[];
    float* xs  = sm + XS_OFF;   // [c*64 + p]
    float* qs  = sm + QS_OFF;   // [ch*65 + p]
    float* stg = sm + ST_OFF;   // staging / attn

    const int tid = threadIdx.x;
    const int win = blockIdx.x;
    const int b   = win >> 10;
    const int wh  = (win >> 5) & 31;
    const int ww  = win & 31;

    const int h0 = wh * WS + SHIFT;   // rolled-coordinate base (mod 256)
    const int w0 = ww * WS + SHIFT;

    // ---------------- load x window (applies the -SHIFT roll) ----------------
    for (int idx = tid; idx < CDIM * PIX; idx += 256) {
        const int c = idx >> 6;
        const int p = idx & 63;
        const int gh = (h0 + (p >> 3)) & 255;
        const int gw = (w0 + (p & 7)) & 255;
        xs[idx] = x[((size_t)(b * CDIM + c) * HWDIM + gh) * HWDIM + gw];
    }
    __syncthreads();

    const int po  = tid & 31;   // pixel lane: handles p = po and po+32
    const int oco = tid >> 5;   // 0..7 (uniform within a warp)

    // -------- qkv 1x1 conv (576x192 GEMM) + depthwise 3x3, in 9 chunks of 64 oc --------
    for (int ch = 0; ch < 9; ++ch) {
        const int ocb = ch * 64;
        float acc0[8], acc1[8];
        #pragma unroll
        for (int j = 0; j < 8; ++j) { acc0[j] = 0.f; acc1[j] = 0.f; }

        const float* Wb = qkv_w + (size_t)(ocb + oco) * CDIM;
        #pragma unroll 2
        for (int c = 0; c < CDIM; c += 4) {
            float4 wv[8];
            #pragma unroll
            for (int j = 0; j < 8; ++j)
                wv[j] = *(const float4*)(Wb + (size_t)j * (8 * CDIM) + c);
            #pragma unroll
            for (int i = 0; i < 4; ++i) {
                const float xa = xs[(c + i) * 64 + po];
                const float xb = xs[(c + i) * 64 + po + 32];
                #pragma unroll
                for (int j = 0; j < 8; ++j) {
                    const float wji = (&wv[j].x)[i];
                    acc0[j] += wji * xa;
                    acc1[j] += wji * xb;
                }
            }
        }
        #pragma unroll
        for (int j = 0; j < 8; ++j) {
            stg[(oco + 8 * j) * 64 + po]      = acc0[j];
            stg[(oco + 8 * j) * 64 + po + 32] = acc1[j];
        }
        __syncthreads();

        // depthwise 3x3 with zero padding at the window boundary.
        // 256 threads = 4 local channels x 64 pixels per iteration.
        const int pl  = tid & 63;
        const int cl0 = tid >> 6;           // 0..3
        const int r   = pl >> 3;
        const int cc  = pl & 7;
        for (int it = 0; it < 16; ++it) {
            const int lc = it * 4 + cl0;    // 0..63
            const int gc = ocb + lc;
            const float* wd = dw_w + gc * 9;
            const float* s  = stg + lc * 64;
            float acc = 0.f;
            #pragma unroll
            for (int dr = -1; dr <= 1; ++dr) {
                const int rr = r + dr;
                if (rr < 0 || rr >= 8) continue;
                #pragma unroll
                for (int dc = -1; dc <= 1; ++dc) {
                    const int c2 = cc + dc;
                    if (c2 < 0 || c2 >= 8) continue;
                    acc += s[rr * 8 + c2] * wd[(dr + 1) * 3 + (dc + 1)];
                }
            }
            qs[gc * 65 + pl] = acc;
        }
        __syncthreads();
    }

    // ---------------- channel attention: one warp per head ----------------
    const int lane = tid & 31;
    const int widx = tid >> 5;
    float* ao = xs;   // reuse x-window region for attention output [c*64 + p]

    if (widx < HEADS) {
        const int h = widx;
        const float* q = qs + (h * CPH) * 65;
        const float* k = qs + (CDIM + h * CPH) * 65;
        const float* v = qs + (2 * CDIM + h * CPH) * 65;
        const float temp = temperature[h];
        float* attn_s = stg + h * 1024;     // 32x32 attention matrix for this head

        // row L2 norms; lane == row index; cache this lane's k-row in registers
        float sq = 0.f, sk = 0.f;
        float krow[64];
        #pragma unroll
        for (int n = 0; n < 64; ++n) {
            const float a  = q[lane * 65 + n];
            const float bb = k[lane * 65 + n];
            sq += a * a;
            sk += bb * bb;
            krow[n] = bb;
        }
        const float rq = 1.f / fmaxf(sqrtf(sq), 1e-12f);
        const float rk = 1.f / fmaxf(sqrtf(sk), 1e-12f);

        for (int r0 = 0; r0 < 32; ++r0) {
            float a = 0.f;
            #pragma unroll
            for (int n = 0; n < 64; ++n)
                a += q[r0 * 65 + n] * krow[n];   // q row broadcast via LDS
            const float rq_r = __shfl_sync(0xffffffffu, rq, r0);
            a *= rq_r * rk * temp;
            // softmax across lanes (lane == d)
            float m = a;
            #pragma unroll
            for (int o = 16; o; o >>= 1) m = fmaxf(m, __shfl_xor_sync(0xffffffffu, m, o));
            const float e = __expf(a - m);
            float s2 = e;
            #pragma unroll
            for (int o = 16; o; o >>= 1) s2 += __shfl_xor_sync(0xffffffffu, s2, o);
            attn_s[r0 * 32 + lane] = e / s2;
        }

        // out = attn @ v : lane caches v columns n=lane and n=lane+32
        float vc0[32], vc1[32];
        #pragma unroll
        for (int d = 0; d < 32; ++d) {
            vc0[d] = v[d * 65 + lane];
            vc1[d] = v[d * 65 + lane + 32];
        }
        for (int r0 = 0; r0 < 32; ++r0) {
            float o0 = 0.f, o1 = 0.f;
            #pragma unroll
            for (int d = 0; d < 32; ++d) {
                const float arr = attn_s[r0 * 32 + d];   // broadcast
                o0 += arr * vc0[d];
                o1 += arr * vc1[d];
            }
            ao[(h * CPH + r0) * 64 + lane]      = o0;
            ao[(h * CPH + r0) * 64 + lane + 32] = o1;
        }
    }
    __syncthreads();

    // ---------------- project_out 1x1 (192x192 GEMM) + reverse roll store ----------------
    for (int ch = 0; ch < 3; ++ch) {
        const int ocb = ch * 64;
        float acc0[8], acc1[8];
        #pragma unroll
        for (int j = 0; j < 8; ++j) { acc0[j] = 0.f; acc1[j] = 0.f; }

        const float* Pb = proj_w + (size_t)(ocb + oco) * CDIM;
        #pragma unroll 2
        for (int c = 0; c < CDIM; c += 4) {
            float4 wv[8];
            #pragma unroll
            for (int j = 0; j < 8; ++j)
                wv[j] = *(const float4*)(Pb + (size_t)j * (8 * CDIM) + c);
            #pragma unroll
            for (int i = 0; i < 4; ++i) {
                const float xa = ao[(c + i) * 64 + po];
                const float xb = ao[(c + i) * 64 + po + 32];
                #pragma unroll
                for (int j = 0; j < 8; ++j) {
                    const float wji = (&wv[j].x)[i];
                    acc0[j] += wji * xa;
                    acc1[j] += wji * xb;
                }
            }
        }
        #pragma unroll
        for (int j = 0; j < 8; ++j) {
            const int oc = ocb + oco + 8 * j;
            {
                const int p = po;
                const int gh = (h0 + (p >> 3)) & 255;
                const int gw = (w0 + (p & 7)) & 255;
                out[((size_t)(b * CDIM + oc) * HWDIM + gh) * HWDIM + gw] = acc0[j];
            }
            {
                const int p = po + 32;
                const int gh = (h0 + (p >> 3)) & 255;
                const int gw = (w0 + (p & 7)) & 255;
                out[((size_t)(b * CDIM + oc) * HWDIM + gh) * HWDIM + gw] = acc1[j];
            }
        }
    }
}

extern "C" void kernel_launch(void* const* d_in, const int* in_sizes, int n_in,
                              void* d_out, int out_size)
{
    const float* x           = (const float*)d_in[0];
    const float* qkv_w       = (const float*)d_in[1];
    const float* dw_w        = (const float*)d_in[2];
    const float* proj_w      = (const float*)d_in[3];
    const float* temperature = (const float*)d_in[4];
    float* out               = (float*)d_out;

    const size_t smem_bytes = (size_t)SMEM_FLOATS * sizeof(float);
    cudaFuncSetAttribute(win_attn_kernel,
                         cudaFuncAttributeMaxDynamicSharedMemorySize,
                         (int)smem_bytes);
    win_attn_kernel<<<NWIN, 256, smem_bytes>>>(x, qkv_w, dw_w, proj_w,
                                               temperature, out);
}